// round 16
// baseline (speedup 1.0000x reference)
#include <cuda_runtime.h>
#include <cuda_bf16.h>
#include <cuda_pipeline.h>
#include <math.h>

#define B_SZ 8
#define D_MODEL 2048
#define H_N 16
#define R_DIM 64
#define W_TOT 8192
#define NB 64
#define QKV_COLS 6144

#define OUT_OFF 0
#define M_OFF   (B_SZ * H_N * 128)                       // 16384
#define Z_OFF   (M_OFF + B_SZ * H_N * R_DIM * R_DIM)     // 540672
#define S_OFF   (Z_OFF + B_SZ * H_N * R_DIM)             // 548864

#define LOG2_GAMMA (-0.043943347587597055f)
#define FULL 0xffffffffu

typedef unsigned long long u64;

// -------- scratch (device globals; zero-init, monotone counters) --------
__device__ __align__(16) float g_qkv[B_SZ * QKV_COLS];
__device__ __align__(16) float g_part[B_SZ * H_N * NB];
__device__ __align__(16) float g_mrow2[16 * 768];   // per producer-group copies
__device__ float g_mb2[16 * 3];
__device__ int g_grp[16];
__device__ int g_cntB[B_SZ];

__device__ __forceinline__ float softplusf(float x) {
    return fmaxf(x, 0.0f) + log1pf(expf(-fabsf(x)));
}
__device__ __forceinline__ float geluf(float x) {
    return 0.5f * x * (1.0f + erff(x * 0.70710678118654752440f));
}
__device__ __forceinline__ float sigmoidf(float x) {
    return 1.0f / (1.0f + expf(-x));
}
__device__ __forceinline__ u64 fma2(u64 a, u64 b, u64 c) {
    u64 d;
    asm("fma.rn.f32x2 %0, %1, %2, %3;" : "=l"(d) : "l"(a), "l"(b), "l"(c));
    return d;
}
__device__ __forceinline__ float unpack_sum(u64 a) {
    return __uint_as_float((unsigned)(a & 0xffffffffu))
         + __uint_as_float((unsigned)(a >> 32));
}

// ============================================================
// ONE kernel, grid=128 (b,h), block=512, dyn smem 144KB
// dyn: [0,64K) h matrix (GEMM) then Eq_h|Ek_h (projection)
//      [64K,96K) staged bids
//      [96K,144K) W double-buffer (2 stages x 24KB)
// ============================================================
__global__ void __launch_bounds__(512) k_all(
    const float* __restrict__ x, const float* __restrict__ lg,
    const float* __restrict__ lb, const float* __restrict__ W,
    const float* __restrict__ Kl, const float* __restrict__ Vl,
    const float* __restrict__ bm, const int* __restrict__ bids,
    const int* __restrict__ curp,
    const float* __restrict__ Eq, const float* __restrict__ Ek,
    const float* __restrict__ Ev,
    const float* __restrict__ M, const float* __restrict__ z,
    const float* __restrict__ S_prev,
    const float* __restrict__ r1w, const float* __restrict__ r1b,
    const float* __restrict__ r2w, const float* __restrict__ r2b,
    const float* __restrict__ g1w, const float* __restrict__ g1b,
    const float* __restrict__ g2w, const float* __restrict__ g2b,
    float* __restrict__ out) {

    extern __shared__ __align__(16) char dyn[];
    float4* hsAll = (float4*)dyn;                // [4096]
    int*   bidsS  = (int*)(dyn + 65536);         // [8192]
    float4* wS4   = (float4*)(dyn + 98304);      // [3072] = 2 x 1536

    __shared__ __align__(16) float Ms[4096];     // 16 KB
    __shared__ __align__(16) float Ss[4096];     // 16 KB
    __shared__ __align__(16) float bmS[4096];    // 16 KB (score; then accv64 alias)
    __shared__ __align__(16) float u[256];       // [QL | KL | VL | attn]
    __shared__ __align__(16) float qkvS[384];
    __shared__ __align__(16) float projTmp[384];
    __shared__ __align__(16) float qf[64], zs[64], errv[64], linp[64], outlat[64];
    __shared__ __align__(16) float rh[128], ghp[256];
    __shared__ float partv[8][64];   // also gmA/gsA/gwA scratch after consumption
    __shared__ float epartv[8][64];
    __shared__ float sarr[64];
    __shared__ int widx[512];
    __shared__ int warpCnt[16];
    __shared__ int warpBase[17];
    __shared__ int s_i1, s_i2;
    __shared__ float s_sum;
    __shared__ float sc[8];   // 0:qz 1:p_skip 2:alpha 3:eta 4:theta
    __shared__ float smu[8], sinv[8];

    int bh = blockIdx.x;
    int b = bh >> 4, h = bh & 15;
    int tid = threadIdx.x;
    int warp = tid >> 5, lane = tid & 31;

    // ===== group 0: x matrix =====
    {
        const float4* xg = (const float4*)x;
#pragma unroll
        for (int k = 0; k < 8; ++k)
            __pipeline_memcpy_async(&hsAll[tid + k * 512], &xg[tid + k * 512], 16);
        __pipeline_commit();
    }
    // ===== group 1: M, S, bids, bm-slice, z =====
    {
        const float4* Mg4 = (const float4*)(M + (size_t)bh * 4096);
        const float4* Sg4 = (const float4*)(S_prev + (size_t)bh * 4096);
        float4* Ms4 = (float4*)Ms;
        float4* Ss4 = (float4*)Ss;
        float4* bmS4 = (float4*)bmS;
#pragma unroll
        for (int k = 0; k < 2; ++k) {
            int i = tid + k * 512;
            int n = i >> 4, c = i & 15;
            __pipeline_memcpy_async(&bmS4[i],
                ((const float4*)&bm[(((size_t)n * B_SZ + b) * H_N + h) * 64]) + c, 16);
        }
        const int4* br4 = (const int4*)(bids + b * W_TOT);
        int4* bs4 = (int4*)bidsS;
#pragma unroll
        for (int k = 0; k < 4; ++k)
            __pipeline_memcpy_async(&bs4[tid + k * 512], &br4[tid + k * 512], 16);
#pragma unroll
        for (int k = 0; k < 2; ++k)
            __pipeline_memcpy_async(&Ms4[tid + k * 512], &Mg4[tid + k * 512], 16);
#pragma unroll
        for (int k = 0; k < 2; ++k)
            __pipeline_memcpy_async(&Ss4[tid + k * 512], &Sg4[tid + k * 512], 16);
        if (tid < 16)
            __pipeline_memcpy_async(((float4*)zs) + tid,
                                    ((const float4*)(z + bh * 64)) + tid, 16);
        __pipeline_commit();
    }
    // ===== groups 2,3: W stages 0,1 (stream starts at t=0) =====
    const float4* Wbase4 = (const float4*)W + (size_t)bh * 48 * 512;
#pragma unroll
    for (int st = 0; st < 2; ++st) {
        float4* dst = wS4 + st * 1536;
        const float4* src = Wbase4 + st * 32;
#pragma unroll
        for (int t = 0; t < 3; ++t) {
            int i = tid + t * 512;
            int col = i >> 5, seg = i & 31;
            __pipeline_memcpy_async(&dst[i], &src[(size_t)col * 512 + seg], 16);
        }
        __pipeline_commit();
    }
    __pipeline_wait_prior(3);   // x resident (groups 1..3 may still fly)
    __syncthreads();

    // ===== phase B: LN stats from smem (warps 0-7) =====
    if (warp < 8) {
        int bb = warp;
        float s = 0.0f, ss = 0.0f;
#pragma unroll
        for (int i = 0; i < 16; ++i) {
            float4 v = hsAll[bb * 512 + i * 32 + lane];
            s  += v.x + v.y + v.z + v.w;
            ss += v.x * v.x + v.y * v.y + v.z * v.z + v.w * v.w;
        }
#pragma unroll
        for (int o = 16; o; o >>= 1) {
            s  += __shfl_down_sync(FULL, s, o);
            ss += __shfl_down_sync(FULL, ss, o);
        }
        if (lane == 0) {
            float mu = s * (1.0f / D_MODEL);
            float var = ss * (1.0f / D_MODEL) - mu * mu;
            smu[bb] = mu;
            sinv[bb] = rsqrtf(var + 1e-5f);
        }
    }
    __syncthreads();

    // ===== phase B2: normalize h in place =====
    {
#pragma unroll
        for (int k = 0; k < 8; ++k) {
            int i = tid + k * 512;
            int bb = i >> 9, col = i & 511;
            float4 v = hsAll[i];
            float4 gv = ((const float4*)lg)[col];
            float4 bv = ((const float4*)lb)[col];
            float mu = smu[bb], inv = sinv[bb];
            v.x = (v.x - mu) * inv * gv.x + bv.x;
            v.y = (v.y - mu) * inv * gv.y + bv.y;
            v.z = (v.z - mu) * inv * gv.z + bv.z;
            v.w = (v.w - mu) * inv * gv.w + bv.w;
            hsAll[i] = v;
        }
    }
    __syncthreads();

    // ===== phase C: QKV GEMM, smem W double-buffer, f32x2 FFMA =====
    {
        int colBase = bh * 48 + warp * 3;
        u64 acc2[3][8];
#pragma unroll
        for (int c = 0; c < 3; c++)
#pragma unroll
            for (int bb = 0; bb < 8; bb++) acc2[c][bb] = 0ull;

        const ulonglong2* wSu = (const ulonglong2*)wS4;
        const ulonglong2* hsU = (const ulonglong2*)hsAll;

#pragma unroll
        for (int kk = 0; kk < 16; ++kk) {
            if (kk < 15) __pipeline_wait_prior(1);
            else         __pipeline_wait_prior(0);
            __syncthreads();

            int buf = kk & 1;
            u64 wv[3][2];
#pragma unroll
            for (int c = 0; c < 3; c++) {
                ulonglong2 t = wSu[buf * 1536 + (warp * 3 + c) * 32 + lane];
                wv[c][0] = t.x; wv[c][1] = t.y;
            }
            int k4 = kk * 32 + lane;
#pragma unroll
            for (int bb = 0; bb < 8; bb++) {
                ulonglong2 hv = hsU[bb * 512 + k4];
#pragma unroll
                for (int c = 0; c < 3; c++) {
                    acc2[c][bb] = fma2(wv[c][0], hv.x, acc2[c][bb]);
                    acc2[c][bb] = fma2(wv[c][1], hv.y, acc2[c][bb]);
                }
            }
            __syncthreads();   // buffer fully consumed before refill

            if (kk < 14) {
                float4* dst = wS4 + buf * 1536;
                const float4* src = Wbase4 + (kk + 2) * 32;
#pragma unroll
                for (int t = 0; t < 3; ++t) {
                    int i = tid + t * 512;
                    int col = i >> 5, seg = i & 31;
                    __pipeline_memcpy_async(&dst[i], &src[(size_t)col * 512 + seg], 16);
                }
                __pipeline_commit();
            }
        }
#pragma unroll
        for (int c = 0; c < 3; c++)
#pragma unroll
            for (int bb = 0; bb < 8; bb++) {
                float v = unpack_sum(acc2[c][bb]);
#pragma unroll
                for (int o = 16; o; o >>= 1) v += __shfl_down_sync(FULL, v, o);
                if (lane == 0) g_qkv[bb * QKV_COLS + colBase + c] = v;
            }
    }
    __threadfence();
    __syncthreads();   // hsAll reads done; safe to overwrite

    // ===== cp.async Eq_h | Ek_h into hsAll (overlaps barrier-1 spin) =====
    {
        const float4* eq4 = (const float4*)(Eq + (size_t)h * 8192);
        const float4* ek4 = (const float4*)(Ek + (size_t)h * 8192);
#pragma unroll
        for (int k = 0; k < 4; ++k)
            __pipeline_memcpy_async(&hsAll[tid + k * 512], &eq4[tid + k * 512], 16);
#pragma unroll
        for (int k = 0; k < 4; ++k)
            __pipeline_memcpy_async(&hsAll[2048 + tid + k * 512], &ek4[tid + k * 512], 16);
        __pipeline_commit();
    }

    // ===== per-group mean-rows of g2w (uniform work, before barrier 1) =====
    {
        int grp = bh >> 3, j = bh & 7;
        if (tid < 384) {
            int f = 96 * j + (tid >> 2);       // flat index in [0,768)
            int q = tid & 3;
            int jj = f >> 8, c = f & 255;
            const float* g2 = g2w + (size_t)(jj * 64 + q * 16) * 256 + c;
            float s = 0.0f;
#pragma unroll
            for (int r = 0; r < 16; ++r) s += g2[r * 256];
            s += __shfl_down_sync(FULL, s, 2);
            s += __shfl_down_sync(FULL, s, 1);
            if (q == 0) g_mrow2[grp * 768 + f] = s * (1.0f / 64.0f);
        } else if (j == 0 && tid >= 384 && tid < 387) {
            int w = tid - 384;
            float t = 0.0f;
#pragma unroll
            for (int k = 0; k < 64; ++k) t += g2b[w * 64 + k];
            g_mb2[grp * 3 + w] = t * (1.0f / 64.0f);
        }
    }
    __threadfence();
    __syncthreads();

    // ===== barrier 1 (grouped on producer group h) =====
    if (tid == 0) {
        int t = atomicAdd(&g_grp[bh >> 3], 1);
        int tgt = ((t >> 3) + 1) * 8;
        volatile int* vc = &g_grp[h];
        while (*vc < tgt) { }
        __threadfence();
    }
    __syncthreads();

    // ===== phase D: stage qkv slice, projection (Eq/Ek smem, Ev global) =====
    if (tid < 384) qkvS[tid] = g_qkv[b * QKV_COLS + h * 384 + tid];
    __pipeline_wait_prior(0);   // E slices resident
    __syncthreads();
    if (tid < 384) {
        int half = tid >= 192;
        int o = tid - half * 192;
        int which = o >> 6, r = o & 63;
        const float* E;
        if (which < 2) E = (const float*)hsAll + which * 8192 + half * 4096 + r;
        else           E = Ev + (size_t)h * 8192 + half * 4096 + r;
        const float* vec = qkvS + which * 128 + half * 64;
        float acc = 0.0f;
#pragma unroll 16
        for (int d = 0; d < 64; ++d) acc += vec[d] * E[d * 64];
        projTmp[tid] = acc;
    }
    __syncthreads();
    if (tid < 192) u[tid] = projTmp[tid] + projTmp[tid + 192];
    __syncthreads();

    // ===== phase E: score partials from smem bm =====
    if (tid < 256) {
        int n = tid >> 2, q = tid & 3;
        const float4* mrow = (const float4*)(bmS + n * 64);
        const float4* qv4 = (const float4*)u;
        float p = 0.0f;
#pragma unroll
        for (int j = 0; j < 4; ++j) {
            float4 mv = mrow[q * 4 + j], qv = qv4[q * 4 + j];
            p += mv.x * qv.x + mv.y * qv.y + mv.z * qv.z + mv.w * qv.w;
        }
        p += __shfl_down_sync(FULL, p, 2);
        p += __shfl_down_sync(FULL, p, 1);
        if (q == 0) g_part[(b * H_N + h) * NB + n] = p;
    }
    __threadfence();
    __syncthreads();

    // ===== barrier 2 ARRIVE =====
    int tgt2 = 0;
    if (tid == 0) {
        int t = atomicAdd(&g_cntB[b], 1);
        tgt2 = t - (t & 15) + 16;
    }

    // ===== pre-attention work while peers arrive =====
    {
        int o = tid >> 1, half = tid & 1;
        const float4* wr = (const float4*)(g1w + (size_t)o * 256 + half * 96);
        const float4* uv4 = (const float4*)u + half * 24;
        float a = 0.0f;
#pragma unroll
        for (int k = 0; k < 24; ++k) {
            float4 wv = wr[k], uv = uv4[k];
            a += wv.x * uv.x + wv.y * uv.y + wv.z * uv.z + wv.w * uv.w;
        }
        a += __shfl_down_sync(FULL, a, 1);
        if (half == 0) ghp[o] = a + g1b[o];
    }
    if (tid < 64) qf[tid] = softplusf(u[tid]);
    if (tid >= 256 && tid < 384) {
        int o = tid - 256;
        const float4* wr = (const float4*)(r1w + o * 64);
        const float4* qv = (const float4*)u;
        float a = r1b[o];
#pragma unroll
        for (int k = 0; k < 16; ++k) {
            float4 wv = wr[k], uv = qv[k];
            a += wv.x * uv.x + wv.y * uv.y + wv.z * uv.z + wv.w * uv.w;
        }
        rh[o] = geluf(a);
    }
    __syncthreads();
    {
        int s = tid & 63, g = tid >> 6;
        float a = 0.0f, e = 0.0f;
        for (int r = g; r < 64; r += 8) {
            float mrs = Ms[r * 64 + s];
            a += qf[r] * mrs;
            e += u[64 + r] * mrs;
        }
        partv[g][s] = a;
        epartv[g][s] = e;
    }
    __syncthreads();
    if (warp == 0) {
        float t = qf[lane] * zs[lane] + qf[lane + 32] * zs[lane + 32];
#pragma unroll
        for (int o = 16; o; o >>= 1) t += __shfl_down_sync(FULL, t, o);
        if (lane == 0) sc[0] = t + 1e-6f;
    } else if (warp == 1) {
        float t = 0.0f;
#pragma unroll
        for (int k = 0; k < 4; ++k) t += rh[lane + k * 32] * r2w[lane + k * 32];
#pragma unroll
        for (int o = 16; o; o >>= 1) t += __shfl_down_sync(FULL, t, o);
        if (lane == 0) sc[1] = sigmoidf(t + r2b[0]);
    } else if (warp == 2 || warp == 3) {
        int s = (warp - 2) * 32 + lane;
        float a = 0.0f, e = 0.0f;
#pragma unroll
        for (int g = 0; g < 8; ++g) { a += partv[g][s]; e += epartv[g][s]; }
        linp[s] = a;
        errv[s] = e - u[128 + s];
    }
    __syncthreads();

    // ===== barrier 2 WAIT =====
    if (tid == 0) {
        volatile int* vc = &g_cntB[b];
        while (*vc < tgt2) { }
        __threadfence();
    }
    __syncthreads();

    // ===== score sum + decay, top-2 =====
    if (tid < 256) {
        int n = tid >> 2, p = tid & 3;
        float s = 0.0f;
#pragma unroll
        for (int h2 = p; h2 < H_N; h2 += 4)
            s += g_part[(b * H_N + h2) * NB + n];
        s += __shfl_down_sync(FULL, s, 2);
        s += __shfl_down_sync(FULL, s, 1);
        if (p == 0)
            sarr[n] = s * exp2f((float)(63 - n) * LOG2_GAMMA) * 0.0078125f;
    }
    __syncthreads();
    if (tid < 32) {
        float v0 = sarr[tid], v1 = sarr[tid + 32];
        float bv; int bi;
        if (v0 >= v1) { bv = v0; bi = tid; } else { bv = v1; bi = tid + 32; }
#pragma unroll
        for (int o = 16; o; o >>= 1) {
            float ov = __shfl_down_sync(FULL, bv, o);
            int   oi = __shfl_down_sync(FULL, bi, o);
            if (ov > bv || (ov == bv && oi < bi)) { bv = ov; bi = oi; }
        }
        int i1 = __shfl_sync(FULL, bi, 0);
        float w0 = (tid == i1)      ? -INFINITY : v0;
        float w1 = (tid + 32 == i1) ? -INFINITY : v1;
        float cv; int ci;
        if (w0 >= w1) { cv = w0; ci = tid; } else { cv = w1; ci = tid + 32; }
#pragma unroll
        for (int o = 16; o; o >>= 1) {
            float ov = __shfl_down_sync(FULL, cv, o);
            int   oi = __shfl_down_sync(FULL, ci, o);
            if (ov > cv || (ov == cv && oi < ci)) { cv = ov; ci = oi; }
        }
        if (tid == 0) { s_i1 = i1; s_i2 = ci; }
    }
    __syncthreads();

    // ===== compaction (smem bids -> widx) =====
    int nw;
    {
        int i1 = s_i1, i2 = s_i2, cur = curp[0];
        const int4* bs4 = (const int4*)bidsS;
        unsigned mbits = 0;
        int c = 0;
#pragma unroll
        for (int k = 0; k < 4; ++k) {
            int4 v = bs4[tid * 4 + k];
            if (v.x == i1 || v.x == i2 || v.x == cur) { mbits |= 1u << (k * 4 + 0); c++; }
            if (v.y == i1 || v.y == i2 || v.y == cur) { mbits |= 1u << (k * 4 + 1); c++; }
            if (v.z == i1 || v.z == i2 || v.z == cur) { mbits |= 1u << (k * 4 + 2); c++; }
            if (v.w == i1 || v.w == i2 || v.w == cur) { mbits |= 1u << (k * 4 + 3); c++; }
        }
        int inc = c;
#pragma unroll
        for (int o = 1; o < 32; o <<= 1) {
            int t = __shfl_up_sync(FULL, inc, o);
            if (lane >= o) inc += t;
        }
        if (lane == 31) warpCnt[warp] = inc;
        __syncthreads();
        if (tid == 0) {
            int t = 0;
#pragma unroll
            for (int k = 0; k < 16; ++k) { warpBase[k] = t; t += warpCnt[k]; }
            warpBase[16] = t;
        }
        __syncthreads();
        int off = warpBase[warp] + (inc - c);
        int base = tid * 16;
#pragma unroll
        for (int j = 0; j < 16; ++j)
            if ((mbits >> j) & 1u) widx[off++] = base + j;
        nw = warpBase[16];
    }
    __syncthreads();

    // ===== attention: online softmax, 64 groups of 8 lanes =====
    {
        float (*accv64)[64] = (float(*)[64])bmS;   // bmS dead after score phase
        float* gmA = partv[0];
        float* gsA = partv[1];
        float* gwA = partv[2];

        int grp = tid >> 3, r8 = tid & 7;
        const float4* u4 = (const float4*)u;
        float4 qa = u4[r8 * 2], qb = u4[r8 * 2 + 1];
        float m = -INFINITY, s = 0.0f;
        float4 acc0 = make_float4(0.f, 0.f, 0.f, 0.f);
        float4 acc1 = make_float4(0.f, 0.f, 0.f, 0.f);
        int i = grp;
        bool valid = (i < nw);
        float4 k0v, k1v, v0v, v1v;
        if (valid) {
            size_t ro = ((size_t)bh * W_TOT + widx[i]) * 64 + r8 * 8;
            k0v = *(const float4*)&Kl[ro];
            k1v = *(const float4*)&Kl[ro + 4];
            v0v = *(const float4*)&Vl[ro];
            v1v = *(const float4*)&Vl[ro + 4];
        }
        while (valid) {
            int in = i + 64;
            bool vn = (in < nw);
            float4 kn0, kn1, vn0, vn1;
            if (vn) {
                size_t ro = ((size_t)bh * W_TOT + widx[in]) * 64 + r8 * 8;
                kn0 = *(const float4*)&Kl[ro];
                kn1 = *(const float4*)&Kl[ro + 4];
                vn0 = *(const float4*)&Vl[ro];
                vn1 = *(const float4*)&Vl[ro + 4];
            }
            float d = k0v.x * qa.x + k0v.y * qa.y + k0v.z * qa.z + k0v.w * qa.w
                    + k1v.x * qb.x + k1v.y * qb.y + k1v.z * qb.z + k1v.w * qb.w;
            d += __shfl_xor_sync(FULL, d, 1);
            d += __shfl_xor_sync(FULL, d, 2);
            d += __shfl_xor_sync(FULL, d, 4);
            d *= 0.125f;
            float mn = fmaxf(m, d);
            float rs = expf(m - mn);
            float p  = expf(d - mn);
            s = s * rs + p;
            acc0.x = acc0.x * rs + p * v0v.x;
            acc0.y = acc0.y * rs + p * v0v.y;
            acc0.z = acc0.z * rs + p * v0v.z;
            acc0.w = acc0.w * rs + p * v0v.w;
            acc1.x = acc1.x * rs + p * v1v.x;
            acc1.y = acc1.y * rs + p * v1v.y;
            acc1.z = acc1.z * rs + p * v1v.z;
            acc1.w = acc1.w * rs + p * v1v.w;
            m = mn;
            k0v = kn0; k1v = kn1; v0v = vn0; v1v = vn1;
            i = in; valid = vn;
        }
        ((float4*)&accv64[grp][r8 * 8])[0] = acc0;
        ((float4*)&accv64[grp][r8 * 8])[1] = acc1;
        if (r8 == 0) { gmA[grp] = m; gsA[grp] = s; }
        __syncthreads();
        if (warp == 0) {
            float m0 = gmA[lane], m1 = gmA[lane + 32];
            float mm = fmaxf(m0, m1);
#pragma unroll
            for (int o = 16; o; o >>= 1) mm = fmaxf(mm, __shfl_xor_sync(FULL, mm, o));
            float w0 = (m0 == -INFINITY) ? 0.0f : expf(m0 - mm);
            float w1 = (m1 == -INFINITY) ? 0.0f : expf(m1 - mm);
            gwA[lane] = w0;
            gwA[lane + 32] = w1;
            float dn = gsA[lane] * w0 + gsA[lane + 32] * w1;
#pragma unroll
            for (int o = 16; o; o >>= 1) dn += __shfl_xor_sync(FULL, dn, o);
            if (lane == 0) s_sum = dn;
        }
        __syncthreads();
        if (tid < 64) {
            float a = 0.0f;
#pragma unroll
            for (int g = 0; g < 64; ++g) a += accv64[g][tid] * gwA[g];
            u[192 + tid] = a / s_sum;
        }
    }
    __syncthreads();

    // ===== gh fix-up: gh = gelu(gh_pre + g1w[:,192:256] @ attn) =====
    {
        int o = tid >> 1, half = tid & 1;
        const float4* wr = (const float4*)(g1w + (size_t)o * 256 + 192 + half * 32);
        const float4* uv4 = (const float4*)(u + 192) + half * 8;
        float a = 0.0f;
#pragma unroll
        for (int k = 0; k < 8; ++k) {
            float4 wv = wr[k], uv = uv4[k];
            a += wv.x * uv.x + wv.y * uv.y + wv.z * uv.z + wv.w * uv.w;
        }
        a += __shfl_down_sync(FULL, a, 1);
        if (half == 0) ghp[o] = geluf(ghp[o] + a);
    }
    __syncthreads();

    // ===== alpha/eta/theta via per-group mean rows =====
    if (warp < 3) {
        const float* mr = g_mrow2 + h * 768 + warp * 256;
        float t = 0.0f;
#pragma unroll
        for (int k = 0; k < 8; ++k) t += mr[lane + k * 32] * ghp[lane + k * 32];
#pragma unroll
        for (int o = 16; o; o >>= 1) t += __shfl_down_sync(FULL, t, o);
        if (lane == 0) {
            t += g_mb2[h * 3 + warp];
            sc[2 + warp] = (warp == 0) ? sigmoidf(t) : softplusf(t);
        }
    }
    __syncthreads();

    // ===== out_lat, z_new =====
    if (tid < 64) {
        float l = linp[tid] / sc[0];
        float ps = sc[1];
        outlat[tid] = (1.0f - ps) * u[192 + tid] + ps * l;
        float zn = (1.0f - sc[2]) * zs[tid] + softplusf(u[64 + tid]);
        out[Z_OFF + bh * 64 + tid] = zn;
    }
    __syncthreads();

    // ===== state update + output projection =====
    {
        float eta = sc[3], theta = sc[4], oma = 1.0f - sc[2];
        float4* Mo4 = (float4*)(out + M_OFF + (size_t)bh * 4096);
        float4* So4 = (float4*)(out + S_OFF + (size_t)bh * 4096);
        const float4* ev4 = (const float4*)errv;
        const float4* Ms4 = (const float4*)Ms;
        const float4* Ss4 = (const float4*)Ss;
#pragma unroll
        for (int k = 0; k < 2; ++k) {
            int idx = tid + k * 512;
            int r = idx >> 4, s4 = idx & 15;
            float kl = u[64 + r];
            float4 e = ev4[s4];
            float4 sg = Ss4[idx];
            float4 ms = Ms4[idx];
            float4 sn;
            sn.x = eta * sg.x - theta * (kl * e.x);
            sn.y = eta * sg.y - theta * (kl * e.y);
            sn.z = eta * sg.z - theta * (kl * e.z);
            sn.w = eta * sg.w - theta * (kl * e.w);
            So4[idx] = sn;
            float4 mn;
            mn.x = oma * ms.x + sn.x;
            mn.y = oma * ms.y + sn.y;
            mn.z = oma * ms.z + sn.z;
            mn.w = oma * ms.w + sn.w;
            Mo4[idx] = mn;
        }
    }
    if (tid < 256) {
        int o = tid >> 1, half = tid & 1;
        const float4* er = (const float4*)(Ev + ((size_t)h * 128 + o) * 64) + half * 8;
        const float4* ov = (const float4*)outlat + half * 8;
        float a = 0.0f;
#pragma unroll
        for (int k = 0; k < 8; ++k) {
            float4 e = er[k], oo = ov[k];
            a += e.x * oo.x + e.y * oo.y + e.z * oo.z + e.w * oo.w;
        }
        a += __shfl_down_sync(FULL, a, 1);
        if (half == 0) out[OUT_OFF + b * 2048 + h * 128 + o] = a;
    }
}

// ============================================================
extern "C" void kernel_launch(void* const* d_in, const int* in_sizes, int n_in,
                              void* d_out, int out_size) {
    const float* x     = (const float*)d_in[0];
    const float* ln_g  = (const float*)d_in[1];
    const float* ln_b  = (const float*)d_in[2];
    const float* W_qkv = (const float*)d_in[3];
    const float* E_q   = (const float*)d_in[4];
    const float* E_k   = (const float*)d_in[5];
    const float* E_v   = (const float*)d_in[6];
    const float* K_lat = (const float*)d_in[7];
    const float* V_lat = (const float*)d_in[8];
    const float* bm    = (const float*)d_in[9];
    const float* M     = (const float*)d_in[10];
    const float* z     = (const float*)d_in[11];
    const float* S_prev= (const float*)d_in[12];
    const float* r1w   = (const float*)d_in[13];
    const float* r1b   = (const float*)d_in[14];
    const float* r2w   = (const float*)d_in[15];
    const float* r2b   = (const float*)d_in[16];
    const float* g1w   = (const float*)d_in[17];
    const float* g1b   = (const float*)d_in[18];
    const float* g2w   = (const float*)d_in[19];
    const float* g2b   = (const float*)d_in[20];
    const int*   bids  = (const int*)d_in[21];
    const int*   cur   = (const int*)d_in[22];
    float* out = (float*)d_out;

    static bool attr_done = false;
    if (!attr_done) {
        cudaFuncSetAttribute(k_all, cudaFuncAttributeMaxDynamicSharedMemorySize,
                             147456);
        attr_done = true;
    }

    k_all<<<B_SZ * H_N, 512, 147456>>>(x, ln_g, ln_b, W_qkv,
                                       K_lat, V_lat, bm, bids, cur,
                                       E_q, E_k, E_v, M, z, S_prev,
                                       r1w, r1b, r2w, r2b,
                                       g1w, g1b, g2w, g2b, out);
}

// round 17
// speedup vs baseline: 1.1781x; 1.1781x over previous
#include <cuda_runtime.h>
#include <cuda_bf16.h>
#include <cuda_pipeline.h>
#include <math.h>

#define B_SZ 8
#define D_MODEL 2048
#define H_N 16
#define R_DIM 64
#define W_TOT 8192
#define NB 64
#define QKV_COLS 6144

#define OUT_OFF 0
#define M_OFF   (B_SZ * H_N * 128)                       // 16384
#define Z_OFF   (M_OFF + B_SZ * H_N * R_DIM * R_DIM)     // 540672
#define S_OFF   (Z_OFF + B_SZ * H_N * R_DIM)             // 548864

#define LOG2_GAMMA (-0.043943347587597055f)
#define FULL 0xffffffffu

typedef unsigned long long u64;

// -------- scratch (device globals; zero-init, monotone counters) --------
__device__ __align__(16) float g_qkv[B_SZ * QKV_COLS];
__device__ __align__(16) float g_part[B_SZ * H_N * NB];
__device__ __align__(16) float g_mrow2[16 * 768];   // per producer-group copies
__device__ float g_mb2[16 * 3];
__device__ int g_grp[16];
__device__ int g_cntB[B_SZ];

__device__ __forceinline__ float softplusf(float x) {
    return fmaxf(x, 0.0f) + log1pf(expf(-fabsf(x)));
}
__device__ __forceinline__ float geluf(float x) {
    return 0.5f * x * (1.0f + erff(x * 0.70710678118654752440f));
}
__device__ __forceinline__ float sigmoidf(float x) {
    return 1.0f / (1.0f + expf(-x));
}
__device__ __forceinline__ u64 fma2(u64 a, u64 b, u64 c) {
    u64 d;
    asm("fma.rn.f32x2 %0, %1, %2, %3;" : "=l"(d) : "l"(a), "l"(b), "l"(c));
    return d;
}
__device__ __forceinline__ float unpack_sum(u64 a) {
    return __uint_as_float((unsigned)(a & 0xffffffffu))
         + __uint_as_float((unsigned)(a >> 32));
}

// ============================================================
// ONE kernel, grid=128 (b,h), block=512, dyn smem 96KB
// dyn: [0,64K) h matrix (GEMM) then Eq_h|Ek_h (projection)
//      [64K,96K) staged bids
// ============================================================
__global__ void __launch_bounds__(512) k_all(
    const float* __restrict__ x, const float* __restrict__ lg,
    const float* __restrict__ lb, const float* __restrict__ W,
    const float* __restrict__ Kl, const float* __restrict__ Vl,
    const float* __restrict__ bm, const int* __restrict__ bids,
    const int* __restrict__ curp,
    const float* __restrict__ Eq, const float* __restrict__ Ek,
    const float* __restrict__ Ev,
    const float* __restrict__ M, const float* __restrict__ z,
    const float* __restrict__ S_prev,
    const float* __restrict__ r1w, const float* __restrict__ r1b,
    const float* __restrict__ r2w, const float* __restrict__ r2b,
    const float* __restrict__ g1w, const float* __restrict__ g1b,
    const float* __restrict__ g2w, const float* __restrict__ g2b,
    float* __restrict__ out) {

    extern __shared__ __align__(16) char dyn[];
    float4* hsAll = (float4*)dyn;                // [4096] = 8 batches x 512 float4
    int*   bidsS  = (int*)(dyn + 65536);         // [8192]

    __shared__ __align__(16) float Ms[4096];     // 16 KB
    __shared__ __align__(16) float Ss[4096];     // 16 KB
    __shared__ __align__(16) float bmS[4096];    // 16 KB (score; then accv64 alias)
    __shared__ __align__(16) float u[256];       // [QL | KL | VL | attn]
    __shared__ __align__(16) float qkvS[384];
    __shared__ __align__(16) float projTmp[384];
    __shared__ __align__(16) float qf[64], zs[64], errv[64], linp[64], outlat[64];
    __shared__ __align__(16) float rh[128], ghp[256];
    __shared__ float partv[8][64];   // also gmA/gsA/gwA scratch after consumption
    __shared__ float epartv[8][64];
    __shared__ float sarr[64];
    __shared__ int widx[512];
    __shared__ int warpCnt[16];
    __shared__ int warpBase[17];
    __shared__ int s_i1, s_i2;
    __shared__ float s_sum;
    __shared__ float sc[8];   // 0:qz 1:p_skip 2:alpha 3:eta 4:theta
    __shared__ float smu[8], sinv[8];

    int bh = blockIdx.x;
    int b = bh >> 4, h = bh & 15;
    int tid = threadIdx.x;
    int warp = tid >> 5, lane = tid & 31;

    // ===== phase A1: cp.async the full x matrix (first priority) =====
    {
        const float4* xg = (const float4*)x;
#pragma unroll
        for (int k = 0; k < 8; ++k)
            __pipeline_memcpy_async(&hsAll[tid + k * 512], &xg[tid + k * 512], 16);
        __pipeline_commit();
    }
    // ===== phase A2: cp.async M, S, bids, bm-slice, z =====
    {
        const float4* Mg4 = (const float4*)(M + (size_t)bh * 4096);
        const float4* Sg4 = (const float4*)(S_prev + (size_t)bh * 4096);
        float4* Ms4 = (float4*)Ms;
        float4* Ss4 = (float4*)Ss;
        float4* bmS4 = (float4*)bmS;
#pragma unroll
        for (int k = 0; k < 2; ++k) {
            int i = tid + k * 512;
            int n = i >> 4, c = i & 15;
            __pipeline_memcpy_async(&bmS4[i],
                ((const float4*)&bm[(((size_t)n * B_SZ + b) * H_N + h) * 64]) + c, 16);
        }
        const int4* br4 = (const int4*)(bids + b * W_TOT);
        int4* bs4 = (int4*)bidsS;
#pragma unroll
        for (int k = 0; k < 4; ++k)
            __pipeline_memcpy_async(&bs4[tid + k * 512], &br4[tid + k * 512], 16);
#pragma unroll
        for (int k = 0; k < 2; ++k)
            __pipeline_memcpy_async(&Ms4[tid + k * 512], &Mg4[tid + k * 512], 16);
#pragma unroll
        for (int k = 0; k < 2; ++k)
            __pipeline_memcpy_async(&Ss4[tid + k * 512], &Sg4[tid + k * 512], 16);
        if (tid < 16)
            __pipeline_memcpy_async(((float4*)zs) + tid,
                                    ((const float4*)(z + bh * 64)) + tid, 16);
        __pipeline_commit();
    }
    __pipeline_wait_prior(1);   // x resident in smem
    __syncthreads();

    // ===== phase B: LN stats from smem (warps 0-7) =====
    if (warp < 8) {
        int bb = warp;
        float s = 0.0f, ss = 0.0f;
#pragma unroll
        for (int i = 0; i < 16; ++i) {
            float4 v = hsAll[bb * 512 + i * 32 + lane];
            s  += v.x + v.y + v.z + v.w;
            ss += v.x * v.x + v.y * v.y + v.z * v.z + v.w * v.w;
        }
#pragma unroll
        for (int o = 16; o; o >>= 1) {
            s  += __shfl_down_sync(FULL, s, o);
            ss += __shfl_down_sync(FULL, ss, o);
        }
        if (lane == 0) {
            float mu = s * (1.0f / D_MODEL);
            float var = ss * (1.0f / D_MODEL) - mu * mu;
            smu[bb] = mu;
            sinv[bb] = rsqrtf(var + 1e-5f);
        }
    }
    __syncthreads();

    // ===== phase B2: normalize h in place =====
    {
#pragma unroll
        for (int k = 0; k < 8; ++k) {
            int i = tid + k * 512;
            int bb = i >> 9, col = i & 511;
            float4 v = hsAll[i];
            float4 gv = ((const float4*)lg)[col];
            float4 bv = ((const float4*)lb)[col];
            float mu = smu[bb], inv = sinv[bb];
            v.x = (v.x - mu) * inv * gv.x + bv.x;
            v.y = (v.y - mu) * inv * gv.y + bv.y;
            v.z = (v.z - mu) * inv * gv.z + bv.z;
            v.w = (v.w - mu) * inv * gv.w + bv.w;
            hsAll[i] = v;
        }
    }
    __syncthreads();

    // ===== phase C: QKV GEMM, sync-free, f32x2 packed FFMA =====
    {
        int colBase = bh * 48 + warp * 3;
        u64 acc2[3][8];
#pragma unroll
        for (int c = 0; c < 3; c++)
#pragma unroll
            for (int bb = 0; bb < 8; bb++) acc2[c][bb] = 0ull;

        const float* wp = W + (size_t)colBase * D_MODEL + lane * 4;
        u64 wcur[3][2], wnxt[3][2];
#pragma unroll
        for (int c = 0; c < 3; c++) {
            ulonglong2 wv = *(const ulonglong2*)(wp + (size_t)c * D_MODEL);
            wcur[c][0] = wv.x; wcur[c][1] = wv.y;
        }
#pragma unroll
        for (int kk = 0; kk < 16; ++kk) {
            if (kk < 15) {
#pragma unroll
                for (int c = 0; c < 3; c++) {
                    ulonglong2 wv = *(const ulonglong2*)(wp + (size_t)c * D_MODEL + (kk + 1) * 128);
                    wnxt[c][0] = wv.x; wnxt[c][1] = wv.y;
                }
            }
            int k4 = lane + kk * 32;
#pragma unroll
            for (int bb = 0; bb < 8; bb++) {
                ulonglong2 hv = ((const ulonglong2*)hsAll)[bb * 512 + k4];
#pragma unroll
                for (int c = 0; c < 3; c++) {
                    acc2[c][bb] = fma2(wcur[c][0], hv.x, acc2[c][bb]);
                    acc2[c][bb] = fma2(wcur[c][1], hv.y, acc2[c][bb]);
                }
            }
#pragma unroll
            for (int c = 0; c < 3; c++) { wcur[c][0] = wnxt[c][0]; wcur[c][1] = wnxt[c][1]; }
        }
#pragma unroll
        for (int c = 0; c < 3; c++)
#pragma unroll
            for (int bb = 0; bb < 8; bb++) {
                float v = unpack_sum(acc2[c][bb]);
#pragma unroll
                for (int o = 16; o; o >>= 1) v += __shfl_down_sync(FULL, v, o);
                if (lane == 0) g_qkv[bb * QKV_COLS + colBase + c] = v;
            }
    }
    __syncthreads();   // hsAll reads done; safe to overwrite

    // ===== cp.async Eq_h | Ek_h into hsAll (overlaps barrier-1 spin) =====
    {
        const float4* eq4 = (const float4*)(Eq + (size_t)h * 8192);
        const float4* ek4 = (const float4*)(Ek + (size_t)h * 8192);
#pragma unroll
        for (int k = 0; k < 4; ++k)
            __pipeline_memcpy_async(&hsAll[tid + k * 512], &eq4[tid + k * 512], 16);
#pragma unroll
        for (int k = 0; k < 4; ++k)
            __pipeline_memcpy_async(&hsAll[2048 + tid + k * 512], &ek4[tid + k * 512], 16);
        __pipeline_commit();
    }

    // ===== per-group mean-rows of g2w (uniform work, before barrier 1) =====
    {
        int grp = bh >> 3, j = bh & 7;
        if (tid < 384) {
            int f = 96 * j + (tid >> 2);       // flat index in [0,768)
            int q = tid & 3;
            int jj = f >> 8, c = f & 255;
            const float* g2 = g2w + (size_t)(jj * 64 + q * 16) * 256 + c;
            float s = 0.0f;
#pragma unroll
            for (int r = 0; r < 16; ++r) s += g2[r * 256];
            s += __shfl_down_sync(FULL, s, 2);
            s += __shfl_down_sync(FULL, s, 1);
            if (q == 0) g_mrow2[grp * 768 + f] = s * (1.0f / 64.0f);
        } else if (j == 0 && tid >= 384 && tid < 387) {
            int w = tid - 384;
            float t = 0.0f;
#pragma unroll
            for (int k = 0; k < 64; ++k) t += g2b[w * 64 + k];
            g_mb2[grp * 3 + w] = t * (1.0f / 64.0f);
        }
    }
    __threadfence();
    __syncthreads();

    // ===== barrier 1 (grouped on producer group h) =====
    if (tid == 0) {
        int t = atomicAdd(&g_grp[bh >> 3], 1);
        int tgt = ((t >> 3) + 1) * 8;
        volatile int* vc = &g_grp[h];
        while (*vc < tgt) { }
        __threadfence();
    }
    __syncthreads();

    // ===== phase D: stage qkv slice, projection (Eq/Ek smem, Ev global) =====
    if (tid < 384) qkvS[tid] = g_qkv[b * QKV_COLS + h * 384 + tid];
    __pipeline_wait_prior(0);   // E slices resident
    __syncthreads();
    if (tid < 384) {
        int half = tid >= 192;
        int o = tid - half * 192;
        int which = o >> 6, r = o & 63;
        const float* E;
        if (which < 2) E = (const float*)hsAll + which * 8192 + half * 4096 + r;
        else           E = Ev + (size_t)h * 8192 + half * 4096 + r;
        const float* vec = qkvS + which * 128 + half * 64;
        float acc = 0.0f;
#pragma unroll 16
        for (int d = 0; d < 64; ++d) acc += vec[d] * E[d * 64];
        projTmp[tid] = acc;
    }
    __syncthreads();
    if (tid < 192) u[tid] = projTmp[tid] + projTmp[tid + 192];
    __syncthreads();

    // ===== phase E: score partials from smem bm =====
    if (tid < 256) {
        int n = tid >> 2, q = tid & 3;
        const float4* mrow = (const float4*)(bmS + n * 64);
        const float4* qv4 = (const float4*)u;
        float p = 0.0f;
#pragma unroll
        for (int j = 0; j < 4; ++j) {
            float4 mv = mrow[q * 4 + j], qv = qv4[q * 4 + j];
            p += mv.x * qv.x + mv.y * qv.y + mv.z * qv.z + mv.w * qv.w;
        }
        p += __shfl_down_sync(FULL, p, 2);
        p += __shfl_down_sync(FULL, p, 1);
        if (q == 0) g_part[(b * H_N + h) * NB + n] = p;
    }
    __threadfence();
    __syncthreads();

    // ===== barrier 2 ARRIVE =====
    int tgt2 = 0;
    if (tid == 0) {
        int t = atomicAdd(&g_cntB[b], 1);
        tgt2 = t - (t & 15) + 16;
    }

    // ===== pre-attention work while peers arrive =====
    {
        int o = tid >> 1, half = tid & 1;
        const float4* wr = (const float4*)(g1w + (size_t)o * 256 + half * 96);
        const float4* uv4 = (const float4*)u + half * 24;
        float a = 0.0f;
#pragma unroll
        for (int k = 0; k < 24; ++k) {
            float4 wv = wr[k], uv = uv4[k];
            a += wv.x * uv.x + wv.y * uv.y + wv.z * uv.z + wv.w * uv.w;
        }
        a += __shfl_down_sync(FULL, a, 1);
        if (half == 0) ghp[o] = a + g1b[o];
    }
    if (tid < 64) qf[tid] = softplusf(u[tid]);
    if (tid >= 256 && tid < 384) {
        int o = tid - 256;
        const float4* wr = (const float4*)(r1w + o * 64);
        const float4* qv = (const float4*)u;
        float a = r1b[o];
#pragma unroll
        for (int k = 0; k < 16; ++k) {
            float4 wv = wr[k], uv = qv[k];
            a += wv.x * uv.x + wv.y * uv.y + wv.z * uv.z + wv.w * uv.w;
        }
        rh[o] = geluf(a);
    }
    __syncthreads();
    {
        int s = tid & 63, g = tid >> 6;
        float a = 0.0f, e = 0.0f;
        for (int r = g; r < 64; r += 8) {
            float mrs = Ms[r * 64 + s];
            a += qf[r] * mrs;
            e += u[64 + r] * mrs;
        }
        partv[g][s] = a;
        epartv[g][s] = e;
    }
    __syncthreads();
    if (warp == 0) {
        float t = qf[lane] * zs[lane] + qf[lane + 32] * zs[lane + 32];
#pragma unroll
        for (int o = 16; o; o >>= 1) t += __shfl_down_sync(FULL, t, o);
        if (lane == 0) sc[0] = t + 1e-6f;
    } else if (warp == 1) {
        float t = 0.0f;
#pragma unroll
        for (int k = 0; k < 4; ++k) t += rh[lane + k * 32] * r2w[lane + k * 32];
#pragma unroll
        for (int o = 16; o; o >>= 1) t += __shfl_down_sync(FULL, t, o);
        if (lane == 0) sc[1] = sigmoidf(t + r2b[0]);
    } else if (warp == 2 || warp == 3) {
        int s = (warp - 2) * 32 + lane;
        float a = 0.0f, e = 0.0f;
#pragma unroll
        for (int g = 0; g < 8; ++g) { a += partv[g][s]; e += epartv[g][s]; }
        linp[s] = a;
        errv[s] = e - u[128 + s];
    }
    __syncthreads();

    // ===== barrier 2 WAIT =====
    if (tid == 0) {
        volatile int* vc = &g_cntB[b];
        while (*vc < tgt2) { }
        __threadfence();
    }
    __syncthreads();

    // ===== score sum + decay, top-2 =====
    if (tid < 256) {
        int n = tid >> 2, p = tid & 3;
        float s = 0.0f;
#pragma unroll
        for (int h2 = p; h2 < H_N; h2 += 4)
            s += g_part[(b * H_N + h2) * NB + n];
        s += __shfl_down_sync(FULL, s, 2);
        s += __shfl_down_sync(FULL, s, 1);
        if (p == 0)
            sarr[n] = s * exp2f((float)(63 - n) * LOG2_GAMMA) * 0.0078125f;
    }
    __syncthreads();
    if (tid < 32) {
        float v0 = sarr[tid], v1 = sarr[tid + 32];
        float bv; int bi;
        if (v0 >= v1) { bv = v0; bi = tid; } else { bv = v1; bi = tid + 32; }
#pragma unroll
        for (int o = 16; o; o >>= 1) {
            float ov = __shfl_down_sync(FULL, bv, o);
            int   oi = __shfl_down_sync(FULL, bi, o);
            if (ov > bv || (ov == bv && oi < bi)) { bv = ov; bi = oi; }
        }
        int i1 = __shfl_sync(FULL, bi, 0);
        float w0 = (tid == i1)      ? -INFINITY : v0;
        float w1 = (tid + 32 == i1) ? -INFINITY : v1;
        float cv; int ci;
        if (w0 >= w1) { cv = w0; ci = tid; } else { cv = w1; ci = tid + 32; }
#pragma unroll
        for (int o = 16; o; o >>= 1) {
            float ov = __shfl_down_sync(FULL, cv, o);
            int   oi = __shfl_down_sync(FULL, ci, o);
            if (ov > cv || (ov == cv && oi < ci)) { cv = ov; ci = oi; }
        }
        if (tid == 0) { s_i1 = i1; s_i2 = ci; }
    }
    __syncthreads();

    // ===== compaction (smem bids -> widx) =====
    int nw;
    {
        int i1 = s_i1, i2 = s_i2, cur = curp[0];
        const int4* bs4 = (const int4*)bidsS;
        unsigned mbits = 0;
        int c = 0;
#pragma unroll
        for (int k = 0; k < 4; ++k) {
            int4 v = bs4[tid * 4 + k];
            if (v.x == i1 || v.x == i2 || v.x == cur) { mbits |= 1u << (k * 4 + 0); c++; }
            if (v.y == i1 || v.y == i2 || v.y == cur) { mbits |= 1u << (k * 4 + 1); c++; }
            if (v.z == i1 || v.z == i2 || v.z == cur) { mbits |= 1u << (k * 4 + 2); c++; }
            if (v.w == i1 || v.w == i2 || v.w == cur) { mbits |= 1u << (k * 4 + 3); c++; }
        }
        int inc = c;
#pragma unroll
        for (int o = 1; o < 32; o <<= 1) {
            int t = __shfl_up_sync(FULL, inc, o);
            if (lane >= o) inc += t;
        }
        if (lane == 31) warpCnt[warp] = inc;
        __syncthreads();
        if (tid == 0) {
            int t = 0;
#pragma unroll
            for (int k = 0; k < 16; ++k) { warpBase[k] = t; t += warpCnt[k]; }
            warpBase[16] = t;
        }
        __syncthreads();
        int off = warpBase[warp] + (inc - c);
        int base = tid * 16;
#pragma unroll
        for (int j = 0; j < 16; ++j)
            if ((mbits >> j) & 1u) widx[off++] = base + j;
        nw = warpBase[16];
    }
    __syncthreads();

    // ===== attention: online softmax, 64 groups of 8 lanes, prefetched =====
    {
        float (*accv64)[64] = (float(*)[64])bmS;   // bmS dead after score phase
        float* gmA = partv[0];
        float* gsA = partv[1];
        float* gwA = partv[2];

        int grp = tid >> 3, r8 = tid & 7;
        const float4* u4 = (const float4*)u;
        float4 qa = u4[r8 * 2], qb = u4[r8 * 2 + 1];
        float m = -INFINITY, s = 0.0f;
        float4 acc0 = make_float4(0.f, 0.f, 0.f, 0.f);
        float4 acc1 = make_float4(0.f, 0.f, 0.f, 0.f);
        int i = grp;
        bool valid = (i < nw);
        float4 k0v, k1v, v0v, v1v;
        if (valid) {
            size_t ro = ((size_t)bh * W_TOT + widx[i]) * 64 + r8 * 8;
            k0v = *(const float4*)&Kl[ro];
            k1v = *(const float4*)&Kl[ro + 4];
            v0v = *(const float4*)&Vl[ro];
            v1v = *(const float4*)&Vl[ro + 4];
        }
        while (valid) {
            int in = i + 64;
            bool vn = (in < nw);
            float4 kn0, kn1, vn0, vn1;
            if (vn) {
                size_t ro = ((size_t)bh * W_TOT + widx[in]) * 64 + r8 * 8;
                kn0 = *(const float4*)&Kl[ro];
                kn1 = *(const float4*)&Kl[ro + 4];
                vn0 = *(const float4*)&Vl[ro];
                vn1 = *(const float4*)&Vl[ro + 4];
            }
            float d = k0v.x * qa.x + k0v.y * qa.y + k0v.z * qa.z + k0v.w * qa.w
                    + k1v.x * qb.x + k1v.y * qb.y + k1v.z * qb.z + k1v.w * qb.w;
            d += __shfl_xor_sync(FULL, d, 1);
            d += __shfl_xor_sync(FULL, d, 2);
            d += __shfl_xor_sync(FULL, d, 4);
            d *= 0.125f;
            float mn = fmaxf(m, d);
            float rs = expf(m - mn);
            float p  = expf(d - mn);
            s = s * rs + p;
            acc0.x = acc0.x * rs + p * v0v.x;
            acc0.y = acc0.y * rs + p * v0v.y;
            acc0.z = acc0.z * rs + p * v0v.z;
            acc0.w = acc0.w * rs + p * v0v.w;
            acc1.x = acc1.x * rs + p * v1v.x;
            acc1.y = acc1.y * rs + p * v1v.y;
            acc1.z = acc1.z * rs + p * v1v.z;
            acc1.w = acc1.w * rs + p * v1v.w;
            m = mn;
            k0v = kn0; k1v = kn1; v0v = vn0; v1v = vn1;
            i = in; valid = vn;
        }
        ((float4*)&accv64[grp][r8 * 8])[0] = acc0;
        ((float4*)&accv64[grp][r8 * 8])[1] = acc1;
        if (r8 == 0) { gmA[grp] = m; gsA[grp] = s; }
        __syncthreads();
        if (warp == 0) {
            float m0 = gmA[lane], m1 = gmA[lane + 32];
            float mm = fmaxf(m0, m1);
#pragma unroll
            for (int o = 16; o; o >>= 1) mm = fmaxf(mm, __shfl_xor_sync(FULL, mm, o));
            float w0 = (m0 == -INFINITY) ? 0.0f : expf(m0 - mm);
            float w1 = (m1 == -INFINITY) ? 0.0f : expf(m1 - mm);
            gwA[lane] = w0;
            gwA[lane + 32] = w1;
            float dn = gsA[lane] * w0 + gsA[lane + 32] * w1;
#pragma unroll
            for (int o = 16; o; o >>= 1) dn += __shfl_xor_sync(FULL, dn, o);
            if (lane == 0) s_sum = dn;
        }
        __syncthreads();
        if (tid < 64) {
            float a = 0.0f;
#pragma unroll
            for (int g = 0; g < 64; ++g) a += accv64[g][tid] * gwA[g];
            u[192 + tid] = a / s_sum;
        }
    }
    __syncthreads();

    // ===== gh fix-up: gh = gelu(gh_pre + g1w[:,192:256] @ attn) =====
    {
        int o = tid >> 1, half = tid & 1;
        const float4* wr = (const float4*)(g1w + (size_t)o * 256 + 192 + half * 32);
        const float4* uv4 = (const float4*)(u + 192) + half * 8;
        float a = 0.0f;
#pragma unroll
        for (int k = 0; k < 8; ++k) {
            float4 wv = wr[k], uv = uv4[k];
            a += wv.x * uv.x + wv.y * uv.y + wv.z * uv.z + wv.w * uv.w;
        }
        a += __shfl_down_sync(FULL, a, 1);
        if (half == 0) ghp[o] = geluf(ghp[o] + a);
    }
    __syncthreads();

    // ===== alpha/eta/theta via per-group mean rows =====
    if (warp < 3) {
        const float* mr = g_mrow2 + h * 768 + warp * 256;
        float t = 0.0f;
#pragma unroll
        for (int k = 0; k < 8; ++k) t += mr[lane + k * 32] * ghp[lane + k * 32];
#pragma unroll
        for (int o = 16; o; o >>= 1) t += __shfl_down_sync(FULL, t, o);
        if (lane == 0) {
            t += g_mb2[h * 3 + warp];
            sc[2 + warp] = (warp == 0) ? sigmoidf(t) : softplusf(t);
        }
    }
    __syncthreads();

    // ===== out_lat, z_new =====
    if (tid < 64) {
        float l = linp[tid] / sc[0];
        float ps = sc[1];
        outlat[tid] = (1.0f - ps) * u[192 + tid] + ps * l;
        float zn = (1.0f - sc[2]) * zs[tid] + softplusf(u[64 + tid]);
        out[Z_OFF + bh * 64 + tid] = zn;
    }
    __syncthreads();

    // ===== state update + output projection =====
    {
        float eta = sc[3], theta = sc[4], oma = 1.0f - sc[2];
        float4* Mo4 = (float4*)(out + M_OFF + (size_t)bh * 4096);
        float4* So4 = (float4*)(out + S_OFF + (size_t)bh * 4096);
        const float4* ev4 = (const float4*)errv;
        const float4* Ms4 = (const float4*)Ms;
        const float4* Ss4 = (const float4*)Ss;
#pragma unroll
        for (int k = 0; k < 2; ++k) {
            int idx = tid + k * 512;
            int r = idx >> 4, s4 = idx & 15;
            float kl = u[64 + r];
            float4 e = ev4[s4];
            float4 sg = Ss4[idx];
            float4 ms = Ms4[idx];
            float4 sn;
            sn.x = eta * sg.x - theta * (kl * e.x);
            sn.y = eta * sg.y - theta * (kl * e.y);
            sn.z = eta * sg.z - theta * (kl * e.z);
            sn.w = eta * sg.w - theta * (kl * e.w);
            So4[idx] = sn;
            float4 mn;
            mn.x = oma * ms.x + sn.x;
            mn.y = oma * ms.y + sn.y;
            mn.z = oma * ms.z + sn.z;
            mn.w = oma * ms.w + sn.w;
            Mo4[idx] = mn;
        }
    }
    if (tid < 256) {
        int o = tid >> 1, half = tid & 1;
        const float4* er = (const float4*)(Ev + ((size_t)h * 128 + o) * 64) + half * 8;
        const float4* ov = (const float4*)outlat + half * 8;
        float a = 0.0f;
#pragma unroll
        for (int k = 0; k < 8; ++k) {
            float4 e = er[k], oo = ov[k];
            a += e.x * oo.x + e.y * oo.y + e.z * oo.z + e.w * oo.w;
        }
        a += __shfl_down_sync(FULL, a, 1);
        if (half == 0) out[OUT_OFF + b * 2048 + h * 128 + o] = a;
    }
}

// ============================================================
extern "C" void kernel_launch(void* const* d_in, const int* in_sizes, int n_in,
                              void* d_out, int out_size) {
    const float* x     = (const float*)d_in[0];
    const float* ln_g  = (const float*)d_in[1];
    const float* ln_b  = (const float*)d_in[2];
    const float* W_qkv = (const float*)d_in[3];
    const float* E_q   = (const float*)d_in[4];
    const float* E_k   = (const float*)d_in[5];
    const float* E_v   = (const float*)d_in[6];
    const float* K_lat = (const float*)d_in[7];
    const float* V_lat = (const float*)d_in[8];
    const float* bm    = (const float*)d_in[9];
    const float* M     = (const float*)d_in[10];
    const float* z     = (const float*)d_in[11];
    const float* S_prev= (const float*)d_in[12];
    const float* r1w   = (const float*)d_in[13];
    const float* r1b   = (const float*)d_in[14];
    const float* r2w   = (const float*)d_in[15];
    const float* r2b   = (const float*)d_in[16];
    const float* g1w   = (const float*)d_in[17];
    const float* g1b   = (const float*)d_in[18];
    const float* g2w   = (const float*)d_in[19];
    const float* g2b   = (const float*)d_in[20];
    const int*   bids  = (const int*)d_in[21];
    const int*   cur   = (const int*)d_in[22];
    float* out = (float*)d_out;

    static bool attr_done = false;
    if (!attr_done) {
        cudaFuncSetAttribute(k_all, cudaFuncAttributeMaxDynamicSharedMemorySize,
                             98304);
        attr_done = true;
    }

    k_all<<<B_SZ * H_N, 512, 98304>>>(x, ln_g, ln_b, W_qkv,
                                      K_lat, V_lat, bm, bids, cur,
                                      E_q, E_k, E_v, M, z, S_prev,
                                      r1w, r1b, r2w, r2b,
                                      g1w, g1b, g2w, g2b, out);
}